// round 7
// baseline (speedup 1.0000x reference)
#include <cuda_runtime.h>
#include <cstdint>
#include <math.h>

#define Sx 512
#define Bx 64
#define Hx 256
#define Lx 6
#define G3 768          // 3*H
#define DHx 512         // 2*H
#define M_TOT (Sx*Bx)   // 32768

typedef unsigned long long ull;

// ---------------- device scratch (static: no allocation allowed) ----------------
__device__ float g_gxT[2][(size_t)Sx*G3*Bx];   // [dir][s][gate*256+j][b] (bias added)
__device__ float g_io[(size_t)Sx*Bx*DHx];      // layer input/output (S,B,2H)
__device__ float g_hG[2][2][16][1024];         // [dir][pp][bgrp][k4*16 + b*4 + k%4]
__device__ unsigned g_sync2[32*64];            // per-group: cnt @ [g*64], gen @ [g*64+32]

// ---------------- acquire/release phase barrier (nb blocks) ----------------
__device__ __forceinline__ void gbar(unsigned* cnt, unsigned* gen, unsigned nb, unsigned phase){
    unsigned old;
    asm volatile("atom.add.acq_rel.gpu.u32 %0,[%1],1;" : "=r"(old) : "l"(cnt) : "memory");
    if (old == nb*phase - 1u){
        asm volatile("st.global.release.gpu.u32 [%0],%1;" :: "l"(gen), "r"(phase) : "memory");
    } else {
        unsigned g;
        do {
            asm volatile("ld.global.acquire.gpu.u32 %0,[%1];" : "=r"(g) : "l"(gen) : "memory");
        } while ((int)(g - phase) < 0);
    }
}

// =================================================================================
// gate_x GEMM (proven): 128x128 tile, BK=8, f32x2 micro-tile, register
// double-buffered global prefetch. Writes transposed gxT with bias added.
// =================================================================================
template<int K>
__global__ void __launch_bounds__(256,2) gatex_gemm(
    const float* __restrict__ xin,
    const float* __restrict__ Wbase,   // [2][768][K]
    const float* __restrict__ bias)    // [2][768]
{
    __shared__ float2 Asd[8][128];
    __shared__ float  Wsf[8][128];

    const int dir = blockIdx.z;
    const float* A = (K == 128) ? xin : g_io;
    const float* W = Wbase + (size_t)dir * G3 * K;
    const int n0 = blockIdx.x * 128;
    const int m0 = blockIdx.y * 128;
    const int tid = threadIdx.x;
    const int row  = tid >> 1;
    const int part = tid & 1;
    const int tx = tid & 15;
    const int ty = tid >> 4;

    ull acc[8][4];
    #pragma unroll
    for (int r = 0; r < 8; r++)
        #pragma unroll
        for (int c = 0; c < 4; c++) acc[r][c] = 0ull;

    const float* Ald = A + (size_t)(m0 + row) * K + part * 4;
    const float* Wld = W + (size_t)(n0 + row) * K + part * 4;

    float4 av = *(const float4*)(Ald);
    float4 wv = *(const float4*)(Wld);

    for (int kt = 0; kt < K; kt += 8){
        const int kb = part * 4;
        Asd[kb+0][row] = make_float2(av.x, av.x);
        Asd[kb+1][row] = make_float2(av.y, av.y);
        Asd[kb+2][row] = make_float2(av.z, av.z);
        Asd[kb+3][row] = make_float2(av.w, av.w);
        Wsf[kb+0][row] = wv.x; Wsf[kb+1][row] = wv.y;
        Wsf[kb+2][row] = wv.z; Wsf[kb+3][row] = wv.w;
        __syncthreads();
        if (kt + 8 < K){
            av = *(const float4*)(Ald + kt + 8);
            wv = *(const float4*)(Wld + kt + 8);
        }
        #pragma unroll
        for (int k = 0; k < 8; k++){
            ull a2[8], w2[4];
            #pragma unroll
            for (int r = 0; r < 8; r++)
                a2[r] = *(const ull*)&Asd[k][ty + 16*r];
            #pragma unroll
            for (int c = 0; c < 4; c++)
                w2[c] = *(const ull*)&Wsf[k][2*tx + 32*c];
            #pragma unroll
            for (int r = 0; r < 8; r++)
                #pragma unroll
                for (int c = 0; c < 4; c++)
                    asm("fma.rn.f32x2 %0,%1,%2,%0;"
                        : "+l"(acc[r][c]) : "l"(a2[r]), "l"(w2[c]));
        }
        __syncthreads();
    }

    float* out = g_gxT[dir];
    const float* bs = bias + dir * G3 + n0;
    #pragma unroll
    for (int c = 0; c < 4; c++){
        const int nn = 2*tx + 32*c;
        const float bbx = bs[nn], bby = bs[nn+1];
        #pragma unroll
        for (int r = 0; r < 8; r++){
            const int m = m0 + ty + 16*r;
            const int s = m >> 6;
            const int b = m & 63;
            float lo, hi;
            asm("mov.b64 {%0,%1},%2;" : "=f"(lo), "=f"(hi) : "l"(acc[r][c]));
            out[((size_t)s*G3 + n0 + nn    )*Bx + b] = lo + bbx;
            out[((size_t)s*G3 + n0 + nn + 1)*Bx + b] = hi + bby;
        }
    }
}

// =================================================================================
// Persistent GRU layer, BATCH-PARTITIONED: 128 blocks = 32 groups x 4.
// Group = (dir, 4 batches). Block q in group owns j-quarter [64q, 64q+64) and its
// 192x256 W_hh slice in dynamic SMEM (196KB, [g][k4][j][4] conflict-free layout).
// Thread = (j_local, b): computes FULL-K r/z/n dots (no reduction) + epilogue.
// Per step: 4-block L2 barrier, 4KB h copy to SMEM, 64 k4-iters
// (1 LDS.128 h + 3 LDS.128 W + 6 FFMA2), 1KB hnew exchange. h double-buffered.
// =================================================================================
#define WS_FLOATS 49152                 // 3*64*64*4
#define SMEM_GRU ((WS_FLOATS + 1024) * 4)

__global__ void __launch_bounds__(256,1) gru_layer(
    const float* __restrict__ h0_l,    // [2][B][H]
    const float* __restrict__ whh_l,   // [2][768][256]
    const float* __restrict__ bhh_l,   // [2][768]
    float* __restrict__ hn_out)        // [2][B][H] slice of d_out
{
    extern __shared__ float sm[];
    float* ws = sm;                    // [g][k4][j][4]
    float* hs = sm + WS_FLOATS;        // [k4][b][4]

    const int bx    = blockIdx.x;      // 0..127
    const int grp   = bx >> 2;         // 0..31
    const int q     = bx & 3;          // j-quarter
    const int dir   = grp >> 4;
    const int bgrp  = grp & 15;
    const int tid   = threadIdx.x;
    const int b     = tid & 3;
    const int jl    = tid >> 2;        // 0..63
    const int jglob = q*64 + jl;
    const int bglob = bgrp*4 + b;

    // stage W slice: ws[((g*64 + k4)*64 + j)*4 + e] = W[dir][g*256+q*64+j][k4*4+e]
    for (int i = tid; i < WS_FLOATS; i += 256){
        const int e  = i & 3;
        const int j  = (i >> 2) & 63;
        const int k4 = (i >> 8) & 63;
        const int g  = i >> 14;
        ws[i] = whh_l[((size_t)dir*G3 + g*Hx + q*64 + j)*Hx + k4*4 + e];
    }

    // stage h0 (this block's j-quarter) into group h buffer, pp=0
    g_hG[dir][0][bgrp][(jglob >> 2)*16 + b*4 + (jglob & 3)] =
        h0_l[(size_t)dir*Bx*Hx + (size_t)bglob*Hx + jglob];

    const float br = bhh_l[dir*G3 + jglob];
    const float bz = bhh_l[dir*G3 + Hx + jglob];
    const float bn = bhh_l[dir*G3 + 2*Hx + jglob];

    unsigned* cnt = &g_sync2[grp*64];
    unsigned* gen = &g_sync2[grp*64 + 32];
    unsigned bstep = 1;

    __syncthreads();
    if (tid == 0) gbar(cnt, gen, 4, bstep);
    bstep++;
    __syncthreads();

    const unsigned hsa = (unsigned)__cvta_generic_to_shared(hs) + b*16;
    const unsigned ws0 = (unsigned)__cvta_generic_to_shared(ws) + jl*16;
    const unsigned ws1 = ws0 + 64*64*4*4;      // g=1 base
    const unsigned ws2 = ws1 + 64*64*4*4;      // g=2 base
    const float* gxb = g_gxT[dir];
    const int hidx = (jglob >> 2)*16 + b*4 + (jglob & 3);

    int cur = 0;
    for (int t = 0; t < Sx; t++){
        const int ta = dir ? (Sx - 1 - t) : t;

        // gate_x prefetch (independent of h)
        const float* p = gxb + (size_t)ta*G3*Bx + bglob;
        const float xr = __ldg(p + (size_t)(0*Hx + jglob)*Bx);
        const float xz = __ldg(p + (size_t)(1*Hx + jglob)*Bx);
        const float xn = __ldg(p + (size_t)(2*Hx + jglob)*Bx);

        // copy h(t) (full 256 j, own 4 batches) into SMEM; .cg (cross-SM producer)
        {
            float4 hv;
            asm volatile("ld.global.cg.v4.f32 {%0,%1,%2,%3},[%4];"
                         : "=f"(hv.x), "=f"(hv.y), "=f"(hv.z), "=f"(hv.w)
                         : "l"(g_hG[dir][cur][bgrp] + tid*4));
            *(float4*)(hs + tid*4) = hv;
        }
        __syncthreads();

        const float hprev = hs[hidx];

        // full-K dots for (jglob, b): r, z, n
        ull aR = 0ull, aZ = 0ull, aN = 0ull;
        #pragma unroll 8
        for (int k4 = 0; k4 < 64; k4++){
            ull h01, h23, wA, wB;
            asm volatile("ld.shared.v2.u64 {%0,%1},[%2];"
                         : "=l"(h01), "=l"(h23) : "r"(hsa + k4*64));
            asm volatile("ld.shared.v2.u64 {%0,%1},[%2];"
                         : "=l"(wA), "=l"(wB) : "r"(ws0 + k4*1024));
            asm("fma.rn.f32x2 %0,%1,%2,%0;" : "+l"(aR) : "l"(h01), "l"(wA));
            asm("fma.rn.f32x2 %0,%1,%2,%0;" : "+l"(aR) : "l"(h23), "l"(wB));
            asm volatile("ld.shared.v2.u64 {%0,%1},[%2];"
                         : "=l"(wA), "=l"(wB) : "r"(ws1 + k4*1024));
            asm("fma.rn.f32x2 %0,%1,%2,%0;" : "+l"(aZ) : "l"(h01), "l"(wA));
            asm("fma.rn.f32x2 %0,%1,%2,%0;" : "+l"(aZ) : "l"(h23), "l"(wB));
            asm volatile("ld.shared.v2.u64 {%0,%1},[%2];"
                         : "=l"(wA), "=l"(wB) : "r"(ws2 + k4*1024));
            asm("fma.rn.f32x2 %0,%1,%2,%0;" : "+l"(aN) : "l"(h01), "l"(wA));
            asm("fma.rn.f32x2 %0,%1,%2,%0;" : "+l"(aN) : "l"(h23), "l"(wB));
        }

        float sr, sz, sn;
        {
            float lo, hi;
            asm("mov.b64 {%0,%1},%2;" : "=f"(lo), "=f"(hi) : "l"(aR)); sr = lo + hi;
            asm("mov.b64 {%0,%1},%2;" : "=f"(lo), "=f"(hi) : "l"(aZ)); sz = lo + hi;
            asm("mov.b64 {%0,%1},%2;" : "=f"(lo), "=f"(hi) : "l"(aN)); sn = lo + hi;
        }

        const float r = 1.f / (1.f + __expf(-(xr + sr + br)));
        const float z = 1.f / (1.f + __expf(-(xz + sz + bz)));
        const float nn = tanhf(xn + r * (sn + bn));
        const float hnew = (1.f - z) * nn + z * hprev;

        // publish hnew (own j-quarter) to the OTHER pp buffer
        g_hG[dir][cur ^ 1][bgrp][hidx] = hnew;
        g_io[((size_t)ta*Bx + bglob)*DHx + dir*Hx + jglob] = hnew;
        if (t == Sx - 1)
            hn_out[(size_t)dir*Bx*Hx + (size_t)bglob*Hx + jglob] = hnew;

        __syncthreads();
        if (t < Sx - 1){
            if (tid == 0) gbar(cnt, gen, 4, bstep);
            bstep++;
            __syncthreads();
        }
        cur ^= 1;
    }
}

// =================================================================================
extern "C" void kernel_launch(void* const* d_in, const int* in_sizes, int n_in,
                              void* d_out, int out_size)
{
    const float* x     = (const float*)d_in[0];   // (512,64,128)
    const float* h0    = (const float*)d_in[1];   // (12,64,256)
    const float* w_ih0 = (const float*)d_in[2];   // (2,768,128)
    const float* w_ih  = (const float*)d_in[3];   // (5,2,768,512)
    const float* w_hh  = (const float*)d_in[4];   // (6,2,768,256)
    const float* b_ih  = (const float*)d_in[5];   // (6,2,768)
    const float* b_hh  = (const float*)d_in[6];   // (6,2,768)
    float* out = (float*)d_out;                   // (12,64,256)

    cudaFuncSetAttribute(gru_layer, cudaFuncAttributeMaxDynamicSharedMemorySize, SMEM_GRU);
    void* syncp = nullptr;
    cudaGetSymbolAddress(&syncp, g_sync2);

    for (int layer = 0; layer < Lx; layer++){
        dim3 gg(G3/128, M_TOT/128, 2);
        if (layer == 0){
            gatex_gemm<128><<<gg, 256>>>(x, w_ih0, b_ih);
        } else {
            gatex_gemm<512><<<gg, 256>>>(
                x,
                w_ih + (size_t)(layer-1) * 2 * G3 * 512,
                b_ih + (size_t)layer * 2 * G3);
        }
        cudaMemsetAsync(syncp, 0, 32*64*sizeof(unsigned));
        gru_layer<<<128, 256, SMEM_GRU>>>(
            h0   + (size_t)layer * 2 * Bx * Hx,
            w_hh + (size_t)layer * 2 * G3 * Hx,
            b_hh + (size_t)layer * 2 * G3,
            out  + (size_t)layer * 2 * Bx * Hx);
    }
}

// round 8
// speedup vs baseline: 1.4372x; 1.4372x over previous
#include <cuda_runtime.h>
#include <cstdint>
#include <math.h>

#define Sx 512
#define Bx 64
#define Hx 256
#define Lx 6
#define G3 768          // 3*H
#define DHx 512         // 2*H
#define M_TOT (Sx*Bx)   // 32768

typedef unsigned long long ull;

// ---------------- device scratch (static: no allocation allowed) ----------------
__device__ float g_gxT[2][(size_t)Sx*G3*Bx];          // [dir][s][gate*256+j][b] (bias added)
__device__ float g_io[(size_t)Sx*Bx*DHx];             // layer input/output (S,B,2H)
__device__ __align__(16) float g_hI[2][2][Hx*Bx];     // [dir][pp][k2*128 + b*2 + (k&1)]
__device__ unsigned g_sync[256];                      // dir0: cnt@0 gen@32; dir1: cnt@128 gen@160

// ---------------- acquire/release grid barrier (per-dir) ----------------
__device__ __forceinline__ void gbar(unsigned* cnt, unsigned* gen, unsigned nb, unsigned phase){
    unsigned old;
    asm volatile("atom.add.acq_rel.gpu.u32 %0,[%1],1;" : "=r"(old) : "l"(cnt) : "memory");
    if (old == nb*phase - 1u){
        asm volatile("st.global.release.gpu.u32 [%0],%1;" :: "l"(gen), "r"(phase) : "memory");
    } else {
        unsigned g;
        do {
            asm volatile("ld.global.acquire.gpu.u32 %0,[%1];" : "=r"(g) : "l"(gen) : "memory");
        } while ((int)(g - phase) < 0);
    }
}

__device__ __forceinline__ unsigned f2tf32(float f){
    unsigned u;
    asm("cvt.rna.tf32.f32 %0,%1;" : "=r"(u) : "f"(f));
    return u;
}

// =================================================================================
// gate_x GEMM, tf32 tensor cores: out[dir][s][g][b] = inp . W^T + b_ih.
// Block 128x128, BK=16, 8 warps (2x4), warp tile 64x32 = 16 mma(m16n8k8)/k8.
// Smem stride 136 -> conflict-free frag LDS. Register-prefetch staging.
// =================================================================================
template<int K>
__global__ void __launch_bounds__(256,2) gatex_gemm(
    const float* __restrict__ xin,
    const float* __restrict__ Wbase,   // [2][768][K]
    const float* __restrict__ bias)    // [2][768]
{
    __shared__ unsigned As[16][136];   // [k][m] tf32
    __shared__ unsigned Bs[16][136];   // [k][n] tf32

    const int dir = blockIdx.z;
    const float* A = (K == 128) ? xin : g_io;
    const float* W = Wbase + (size_t)dir * G3 * K;
    const int n0 = blockIdx.x * 128;
    const int m0 = blockIdx.y * 128;
    const int tid = threadIdx.x;
    const int row  = tid >> 1;
    const int part = tid & 1;
    const int lane = tid & 31;
    const int w    = tid >> 5;
    const int wm = (w & 1) * 64;
    const int wn = (w >> 1) * 32;
    const int g = lane >> 2;
    const int t = lane & 3;

    float acc[4][4][4];
    #pragma unroll
    for (int mt = 0; mt < 4; mt++)
        #pragma unroll
        for (int nt = 0; nt < 4; nt++)
            #pragma unroll
            for (int i = 0; i < 4; i++) acc[mt][nt][i] = 0.f;

    const float* Ald = A + (size_t)(m0 + row) * K + part * 4;
    const float* Wld = W + (size_t)(n0 + row) * K + part * 4;

    float4 av0 = *(const float4*)(Ald);
    float4 av1 = *(const float4*)(Ald + 8);
    float4 wv0 = *(const float4*)(Wld);
    float4 wv1 = *(const float4*)(Wld + 8);

    for (int kt = 0; kt < K; kt += 16){
        const int k0 = part * 4;
        As[k0+0][row] = f2tf32(av0.x); As[k0+1][row] = f2tf32(av0.y);
        As[k0+2][row] = f2tf32(av0.z); As[k0+3][row] = f2tf32(av0.w);
        As[k0+8][row] = f2tf32(av1.x); As[k0+9][row] = f2tf32(av1.y);
        As[k0+10][row] = f2tf32(av1.z); As[k0+11][row] = f2tf32(av1.w);
        Bs[k0+0][row] = f2tf32(wv0.x); Bs[k0+1][row] = f2tf32(wv0.y);
        Bs[k0+2][row] = f2tf32(wv0.z); Bs[k0+3][row] = f2tf32(wv0.w);
        Bs[k0+8][row] = f2tf32(wv1.x); Bs[k0+9][row] = f2tf32(wv1.y);
        Bs[k0+10][row] = f2tf32(wv1.z); Bs[k0+11][row] = f2tf32(wv1.w);
        __syncthreads();
        if (kt + 16 < K){
            av0 = *(const float4*)(Ald + kt + 16);
            av1 = *(const float4*)(Ald + kt + 24);
            wv0 = *(const float4*)(Wld + kt + 16);
            wv1 = *(const float4*)(Wld + kt + 24);
        }
        #pragma unroll
        for (int c = 0; c < 2; c++){
            unsigned af[4][4], bf[4][2];
            #pragma unroll
            for (int mt = 0; mt < 4; mt++){
                const int m = wm + mt*16 + g;
                af[mt][0] = As[c*8 + t][m];
                af[mt][1] = As[c*8 + t][m + 8];
                af[mt][2] = As[c*8 + t + 4][m];
                af[mt][3] = As[c*8 + t + 4][m + 8];
            }
            #pragma unroll
            for (int nt = 0; nt < 4; nt++){
                const int n = wn + nt*8 + g;
                bf[nt][0] = Bs[c*8 + t][n];
                bf[nt][1] = Bs[c*8 + t + 4][n];
            }
            #pragma unroll
            for (int mt = 0; mt < 4; mt++)
                #pragma unroll
                for (int nt = 0; nt < 4; nt++)
                    asm volatile(
                        "mma.sync.aligned.m16n8k8.row.col.f32.tf32.tf32.f32 "
                        "{%0,%1,%2,%3},{%4,%5,%6,%7},{%8,%9},{%0,%1,%2,%3};"
                        : "+f"(acc[mt][nt][0]), "+f"(acc[mt][nt][1]),
                          "+f"(acc[mt][nt][2]), "+f"(acc[mt][nt][3])
                        : "r"(af[mt][0]), "r"(af[mt][1]), "r"(af[mt][2]), "r"(af[mt][3]),
                          "r"(bf[nt][0]), "r"(bf[nt][1]));
        }
        __syncthreads();
    }

    float* out = g_gxT[dir];
    const float* bs = bias + dir * G3;
    #pragma unroll
    for (int mt = 0; mt < 4; mt++){
        #pragma unroll
        for (int nt = 0; nt < 4; nt++){
            const int mr = m0 + wm + mt*16 + g;
            const int nc = n0 + wn + nt*8 + 2*t;
            const float b0 = bs[nc], b1 = bs[nc + 1];
            {
                const int s = mr >> 6, b = mr & 63;
                out[((size_t)s*G3 + nc    )*Bx + b] = acc[mt][nt][0] + b0;
                out[((size_t)s*G3 + nc + 1)*Bx + b] = acc[mt][nt][1] + b1;
            }
            {
                const int m2 = mr + 8;
                const int s = m2 >> 6, b = m2 & 63;
                out[((size_t)s*G3 + nc    )*Bx + b] = acc[mt][nt][2] + b0;
                out[((size_t)s*G3 + nc + 1)*Bx + b] = acc[mt][nt][3] + b1;
            }
        }
    }
}

// =================================================================================
// Persistent GRU layer (R6 design, proven): 128 blocks (64/dir), 256 threads.
// Warp ks owns k2-slice [16ks,16ks+16), ALL 4 j columns -> h read exactly once per
// block per step. 4-deep LDG pipeline; one smem reduction pass; distributed epilogue.
// =================================================================================
__global__ void __launch_bounds__(256,1) gru_layer(
    const float* __restrict__ h0_l,    // [2][B][H]
    const float* __restrict__ whh_l,   // [2][768][256]
    const float* __restrict__ bhh_l,   // [2][768]
    float* __restrict__ hn_out)        // [2][B][H] slice of d_out
{
    __shared__ __align__(16) float ws[4][128][8];    // [jj][k2]: wr0,wr1,wz0,wz1,wn0,wn1,pad
    __shared__ float red[8][4][3][64];               // [ks][jj][gate][b]

    const int bx   = blockIdx.x;
    const int dir  = bx >> 6;
    const int jblk = bx & 63;
    const int j0   = jblk * 4;
    const int tid  = threadIdx.x;
    const int bo   = tid & 31;
    const int ks   = tid >> 5;          // warp id = k-slice
    const int jE   = tid >> 6;          // epilogue local j
    const int bE   = tid & 63;          // epilogue batch
    const int jG   = j0 + jE;           // epilogue global j

    // stage packed weights: k = 2*k2 + e
    for (int i = tid; i < 1024; i += 256){
        const int jj = i >> 8, k = i & 255, k2 = k >> 1, e = k & 1;
        const size_t base = ((size_t)dir * G3 + j0 + jj) * Hx + k;
        ws[jj][k2][e]     = whh_l[base];
        ws[jj][k2][2 + e] = whh_l[base + (size_t)Hx*Hx];
        ws[jj][k2][4 + e] = whh_l[base + (size_t)2*Hx*Hx];
    }

    // stage h0 into interleaved layout (this block's 4 j columns)
    {
        const int js = j0 + jE;
        g_hI[dir][0][(js >> 1)*128 + 2*bE + (js & 1)] =
            h0_l[(size_t)dir*Bx*Hx + (size_t)bE*Hx + js];
    }

    const float br = bhh_l[dir*G3 + jG];
    const float bz = bhh_l[dir*G3 + Hx + jG];
    const float bn = bhh_l[dir*G3 + 2*Hx + jG];

    unsigned* cnt = &g_sync[dir*128];
    unsigned* gen = &g_sync[dir*128 + 32];
    unsigned bstep = 1;

    __syncthreads();
    if (tid == 0) gbar(cnt, gen, 64, bstep);
    bstep++;
    __syncthreads();

    unsigned wsa[4];
    #pragma unroll
    for (int jj = 0; jj < 4; jj++)
        wsa[jj] = (unsigned)__cvta_generic_to_shared(&ws[jj][ks*16][0]);

    const float* gxb = g_gxT[dir];
    const int hEoff = (jG >> 1)*128 + 2*bE + (jG & 1);

    int cur = 0;
    for (int t = 0; t < Sx; t++){
        const int ta = dir ? (Sx - 1 - t) : t;

        // per-thread epilogue prefetch (consumed after reduction)
        float xr, xz, xn, hprev;
        {
            const float* p = gxb + (size_t)ta*G3*Bx + bE;
            xr = __ldg(p + (size_t)(0*Hx + jG)*Bx);
            xz = __ldg(p + (size_t)(1*Hx + jG)*Bx);
            xn = __ldg(p + (size_t)(2*Hx + jG)*Bx);
            asm volatile("ld.global.cg.f32 %0,[%1];"
                         : "=f"(hprev) : "l"(g_hI[dir][cur] + hEoff));
        }

        // main dot: 16 k2-iters, 4 j, 3 gates, 2 batches; 4-deep h pipeline
        const float* hp = g_hI[dir][cur] + ks*16*128 + 4*bo;
        ull hc[4][2];
        #pragma unroll
        for (int p = 0; p < 4; p++)
            asm volatile("ld.global.cg.v2.b64 {%0,%1},[%2];"
                         : "=l"(hc[p][0]), "=l"(hc[p][1]) : "l"(hp + p*128));

        ull acc[24];
        #pragma unroll
        for (int i = 0; i < 24; i++) acc[i] = 0ull;

        #pragma unroll
        for (int k2 = 0; k2 < 16; k2++){
            const ull h01 = hc[k2 & 3][0];
            const ull h23 = hc[k2 & 3][1];
            #pragma unroll
            for (int jj = 0; jj < 4; jj++){
                ull wr, wz, wn;
                asm volatile("ld.shared.v2.u64 {%0,%1},[%2];"
                             : "=l"(wr), "=l"(wz) : "r"(wsa[jj] + k2*32));
                asm volatile("ld.shared.u64 %0,[%1];"
                             : "=l"(wn) : "r"(wsa[jj] + k2*32 + 16));
                asm("fma.rn.f32x2 %0,%1,%2,%0;" : "+l"(acc[jj*6+0]) : "l"(h01), "l"(wr));
                asm("fma.rn.f32x2 %0,%1,%2,%0;" : "+l"(acc[jj*6+1]) : "l"(h23), "l"(wr));
                asm("fma.rn.f32x2 %0,%1,%2,%0;" : "+l"(acc[jj*6+2]) : "l"(h01), "l"(wz));
                asm("fma.rn.f32x2 %0,%1,%2,%0;" : "+l"(acc[jj*6+3]) : "l"(h23), "l"(wz));
                asm("fma.rn.f32x2 %0,%1,%2,%0;" : "+l"(acc[jj*6+4]) : "l"(h01), "l"(wn));
                asm("fma.rn.f32x2 %0,%1,%2,%0;" : "+l"(acc[jj*6+5]) : "l"(h23), "l"(wn));
            }
            if (k2 < 12)
                asm volatile("ld.global.cg.v2.b64 {%0,%1},[%2];"
                             : "=l"(hc[k2 & 3][0]), "=l"(hc[k2 & 3][1])
                             : "l"(hp + (k2 + 4)*128));
        }

        // collapse k-parity pairs and publish partials
        #pragma unroll
        for (int jj = 0; jj < 4; jj++)
            #pragma unroll
            for (int g = 0; g < 3; g++){
                float l0, h0f, l1, h1f;
                asm("mov.b64 {%0,%1},%2;" : "=f"(l0), "=f"(h0f) : "l"(acc[jj*6 + 2*g]));
                asm("mov.b64 {%0,%1},%2;" : "=f"(l1), "=f"(h1f) : "l"(acc[jj*6 + 2*g + 1]));
                *(float2*)&red[ks][jj][g][2*bo] = make_float2(l0 + h0f, l1 + h1f);
            }
        __syncthreads();

        // distributed epilogue: thread = (jE, bE); MUFU-fast sigmoid/tanh
        {
            float sr = 0.f, sz = 0.f, sn = 0.f;
            #pragma unroll
            for (int q = 0; q < 8; q++){
                sr += red[q][jE][0][bE];
                sz += red[q][jE][1][bE];
                sn += red[q][jE][2][bE];
            }
            const float r = __fdividef(1.f, 1.f + __expf(-(xr + sr + br)));
            const float z = __fdividef(1.f, 1.f + __expf(-(xz + sz + bz)));
            const float targ = xn + r * (sn + bn);
            const float nn = 1.f - __fdividef(2.f, __expf(2.f*targ) + 1.f);
            const float hnew = (1.f - z) * nn + z * hprev;

            g_hI[dir][cur ^ 1][hEoff] = hnew;
            g_io[((size_t)ta*Bx + bE)*DHx + dir*Hx + jG] = hnew;
            if (t == Sx - 1)
                hn_out[(size_t)dir*Bx*Hx + (size_t)bE*Hx + jG] = hnew;
        }
        __syncthreads();

        if (t < Sx - 1){
            if (tid == 0) gbar(cnt, gen, 64, bstep);
            bstep++;
            __syncthreads();
        }
        cur ^= 1;
    }
}

// =================================================================================
extern "C" void kernel_launch(void* const* d_in, const int* in_sizes, int n_in,
                              void* d_out, int out_size)
{
    const float* x     = (const float*)d_in[0];   // (512,64,128)
    const float* h0    = (const float*)d_in[1];   // (12,64,256)
    const float* w_ih0 = (const float*)d_in[2];   // (2,768,128)
    const float* w_ih  = (const float*)d_in[3];   // (5,2,768,512)
    const float* w_hh  = (const float*)d_in[4];   // (6,2,768,256)
    const float* b_ih  = (const float*)d_in[5];   // (6,2,768)
    const float* b_hh  = (const float*)d_in[6];   // (6,2,768)
    float* out = (float*)d_out;                   // (12,64,256)

    void* syncp = nullptr;
    cudaGetSymbolAddress(&syncp, g_sync);

    for (int layer = 0; layer < Lx; layer++){
        dim3 gg(G3/128, M_TOT/128, 2);
        if (layer == 0){
            gatex_gemm<128><<<gg, 256>>>(x, w_ih0, b_ih);
        } else {
            gatex_gemm<512><<<gg, 256>>>(
                x,
                w_ih + (size_t)(layer-1) * 2 * G3 * 512,
                b_ih + (size_t)layer * 2 * G3);
        }
        cudaMemsetAsync(syncp, 0, 256 * sizeof(unsigned));
        gru_layer<<<128, 256>>>(
            h0   + (size_t)layer * 2 * Bx * Hx,
            w_hh + (size_t)layer * 2 * G3 * Hx,
            b_hh + (size_t)layer * 2 * G3,
            out  + (size_t)layer * 2 * Bx * Hx);
    }
}